// round 1
// baseline (speedup 1.0000x reference)
#include <cuda_runtime.h>

#define BSZ 16
#define NN  96
#define HD  128
#define BN  (BSZ*NN)
#define NPB 8

typedef unsigned long long ull;

// ---------------- scratch (no allocations allowed) ----------------
__device__ float g_h  [BN*HD];
__device__ float g_Hi [BN*HD];
__device__ float g_Hj [BN*HD];
__device__ float g_agg[BN*HD];
__device__ float g_x  [BN*3];
__device__ float g_x0 [BN*3];
__device__ float g_rad[BN*NN];
__device__ float g_d0 [BN*NN];
__device__ float g_cd [BN*NN*3];
__device__ ull   g_W2p[12*HD*HD];   // {w,w}-packed W2 matrices: 8x gWe2 then 4x eWc2

// ---------------- helpers ----------------
__device__ __forceinline__ float silu_f(float x){
    // exact-ish: x * sigmoid(x); MUFU.EX2 + MUFU.RCP, rel err ~1e-6
    float e = __expf(-x);
    return __fdividef(x, 1.0f + e);
}
__device__ __forceinline__ ull pack2(float x, float y){
    ull r; asm("mov.b64 %0, {%1,%2};" : "=l"(r) : "f"(x), "f"(y)); return r;
}
__device__ __forceinline__ void unpack2(ull v, float &x, float &y){
    asm("mov.b64 {%0,%1}, %2;" : "=f"(x), "=f"(y) : "l"(v));
}
__device__ __forceinline__ void ffma2(ull &d, ull a, ull b){
    // packed fp32x2 FMA (Blackwell): d = a*b + d  (2 MACs / instruction)
    asm("fma.rn.f32x2 %0, %1, %2, %0;" : "+l"(d) : "l"(a), "l"(b));
}
union F4U2 { float4 f; ull u[2]; };

// ---------------- prepack W2 matrices into {w,w} u64 ----------------
__global__ void k_prepack(const float* __restrict__ gWe2, const float* __restrict__ eWc2){
    int i = blockIdx.x*blockDim.x + threadIdx.x;
    const int n1 = 8*HD*HD;
    if (i < n1){ float v = gWe2[i];      g_W2p[i] = pack2(v,v); }
    else if (i < 12*HD*HD){ float v = eWc2[i-n1]; g_W2p[i] = pack2(v,v); }
}

// ---------------- init: mask xh, x0/x, h = emb ----------------
__global__ void k_init(const float* __restrict__ xh, const float* __restrict__ t,
                       const float* __restrict__ nm, const float* __restrict__ W_emb,
                       const float* __restrict__ b_emb){
    int n = blockIdx.x; int c = threadIdx.x;
    __shared__ float fs[8];
    float mask = nm[n];
    if (c < 6) fs[c] = xh[n*9 + 3 + c] * mask;
    if (c == 6) fs[6] = t[0];                   // time feature is NOT masked
    if (c < 3){ float v = xh[n*9 + c] * mask; g_x0[n*3+c] = v; g_x[n*3+c] = v; }
    __syncthreads();
    float a = b_emb[c];
    #pragma unroll
    for (int f=0; f<7; f++) a += fs[f] * W_emb[f*HD + c];
    g_h[n*HD + c] = a;
}

// ---------------- radial / d0 / coord_diff ----------------
__global__ void k_radial(int mode){   // mode 0: d0 from x0;  mode 1: radial + coord_diff from x
    int bi = blockIdx.x; int j = threadIdx.x;
    int b = bi / NN;
    const float* X = mode ? g_x : g_x0;
    float xi0 = X[bi*3+0], xi1 = X[bi*3+1], xi2 = X[bi*3+2];
    int nj = b*NN + j;
    float dx = xi0 - X[nj*3+0];
    float dy = xi1 - X[nj*3+1];
    float dz = xi2 - X[nj*3+2];
    float r = dx*dx + dy*dy + dz*dz;
    if (mode){
        g_rad[bi*NN + j] = r;
        float inv = rsqrtf(r + 1e-8f);
        int e = (bi*NN + j)*3;
        g_cd[e+0] = dx*inv; g_cd[e+1] = dy*inv; g_cd[e+2] = dz*inv;
    } else {
        g_d0[bi*NN + j] = r;
    }
}

// ---------------- Hi = h@W1[:128]+b1 ; Hj = h@W1[128:256]  (8 nodes/block) ----------------
__global__ void k_hihj(const float* __restrict__ W1, const float* __restrict__ b1){
    int n0 = blockIdx.x * NPB;
    int c  = threadIdx.x;
    __shared__ float hs[NPB][HD];
    #pragma unroll
    for (int u=0; u<NPB; u++) hs[u][c] = g_h[(n0+u)*HD + c];
    __syncthreads();
    float ai[NPB], aj[NPB];
    float bb = b1[c];
    #pragma unroll
    for (int u=0; u<NPB; u++){ ai[u]=bb; aj[u]=0.f; }
    for (int k=0; k<HD; k++){
        float wi = W1[k*HD + c];
        float wj = W1[(HD+k)*HD + c];
        #pragma unroll
        for (int u=0; u<NPB; u++){ float hv = hs[u][k]; ai[u] += hv*wi; aj[u] += hv*wj; }
    }
    #pragma unroll
    for (int u=0; u<NPB; u++){ g_Hi[(n0+u)*HD+c] = ai[u]; g_Hj[(n0+u)*HD+c] = aj[u]; }
}

// ---------------- node update: u=silu(h@Wn1a + agg@Wn1b + bn1); h=(h+u@Wn2+bn2)*nm ----------------
__global__ void k_node(const float* __restrict__ Wn1, const float* __restrict__ bn1,
                       const float* __restrict__ Wn2, const float* __restrict__ bn2,
                       const float* __restrict__ nm){
    int n0 = blockIdx.x * NPB;
    int c  = threadIdx.x;
    __shared__ float hs[NPB][HD], as[NPB][HD], us[NPB][HD];
    #pragma unroll
    for (int u=0; u<NPB; u++){ hs[u][c] = g_h[(n0+u)*HD+c]; as[u][c] = g_agg[(n0+u)*HD+c]; }
    __syncthreads();
    float acc[NPB];
    float b1v = bn1[c];
    #pragma unroll
    for (int u=0; u<NPB; u++) acc[u] = b1v;
    for (int k=0; k<HD; k++){
        float w1 = Wn1[k*HD + c], w2 = Wn1[(HD+k)*HD + c];
        #pragma unroll
        for (int u=0; u<NPB; u++) acc[u] += hs[u][k]*w1 + as[u][k]*w2;
    }
    #pragma unroll
    for (int u=0; u<NPB; u++) us[u][c] = silu_f(acc[u]);
    __syncthreads();
    float b2v = bn2[c];
    #pragma unroll
    for (int u=0; u<NPB; u++) acc[u] = b2v;
    for (int k=0; k<HD; k++){
        float w = Wn2[k*HD + c];
        #pragma unroll
        for (int u=0; u<NPB; u++) acc[u] += us[u][k]*w;
    }
    #pragma unroll
    for (int u=0; u<NPB; u++) g_h[(n0+u)*HD+c] = (hs[u][c] + acc[u]) * nm[n0+u];
}

// ---------------- edge MLP: one block per (b,i); 48 packed-f32x2 accumulators ----------------
// COORD=0: agg[b,i,c] = sum_j silu(out)*em / 100
// COORD=1: x[b,i] = (x[b,i] + sum_j cd*(phi@w3)*em / 100)*nm
template<int COORD>
__global__ void __launch_bounds__(128,3) k_edge(const float* __restrict__ W1,
        const float* __restrict__ b2, const float* __restrict__ w3,
        const float* __restrict__ em, const float* __restrict__ nm, int widx){
    __shared__ float ms[HD*NN];   // [k][j], XOR-swizzled: word = k*96 + (j ^ ((k&7)<<2)); 48KB
    int bi = blockIdx.x;
    int b  = bi / NN;
    int c  = threadIdx.x;

    // ---- stage 1: m[c][j] = silu(Hi[i,c] + Hj[j,c] + radial*w0 + d0*w1)  (b1 folded in Hi)
    {
        float hi = g_Hi[bi*HD + c];
        float w0 = W1[256*HD + c];
        float w1 = W1[257*HD + c];
        const float* Hjb    = g_Hj + (size_t)b*NN*HD + c;
        const float* radRow = g_rad + bi*NN;
        const float* d0Row  = g_d0  + bi*NN;
        int sw = (c & 7) << 2;
        float* mrow = ms + c*NN;
        for (int j0=0; j0<NN; j0+=4){
            float4 mv;
            mv.x = silu_f(hi + Hjb[(j0+0)*HD] + radRow[j0+0]*w0 + d0Row[j0+0]*w1);
            mv.y = silu_f(hi + Hjb[(j0+1)*HD] + radRow[j0+1]*w0 + d0Row[j0+1]*w1);
            mv.z = silu_f(hi + Hjb[(j0+2)*HD] + radRow[j0+2]*w0 + d0Row[j0+2]*w1);
            mv.w = silu_f(hi + Hjb[(j0+3)*HD] + radRow[j0+3]*w0 + d0Row[j0+3]*w1);
            *reinterpret_cast<float4*>(mrow + (j0 ^ sw)) = mv;
        }
    }
    __syncthreads();

    // ---- stage 2: out[j][c] = sum_k m[k][j] * W2[k][c] + b2[c], all 96 j live (48 f32x2 pairs)
    ull acc[48];
    {
        float bb = b2[c];
        ull bp = pack2(bb, bb);
        #pragma unroll
        for (int p=0; p<48; p++) acc[p] = bp;
    }
    const ull* Wp = g_W2p + (size_t)widx*HD*HD + c;
    const float* mrow = ms;
    for (int kk=0; kk<16; kk++){
        #pragma unroll
        for (int r=0; r<8; r++){          // r = k&7 known at compile time -> immediate LDS offsets
            ull w = *Wp; Wp += HD;
            #pragma unroll
            for (int q=0; q<24; q++){
                F4U2 v;
                v.f = *reinterpret_cast<const float4*>(mrow + ((q*4) ^ (r*4)));
                ffma2(acc[2*q  ], v.u[0], w);
                ffma2(acc[2*q+1], v.u[1], w);
            }
            mrow += NN;
        }
    }

    if (COORD == 0){
        float s = 0.f;
        const float* emrow = em + (size_t)bi*NN;
        #pragma unroll
        for (int p=0; p<48; p++){
            float a0, a1; unpack2(acc[p], a0, a1);      // acc[p] holds j = 2p, 2p+1
            s += silu_f(a0)*emrow[2*p] + silu_f(a1)*emrow[2*p+1];
        }
        g_agg[bi*HD + c] = s * 0.01f;
    } else {
        float wc = w3[c];
        __syncthreads();                                 // everyone done reading ms
        {
            int sw = (c & 7) << 2;
            float* row = ms + c*NN;
            #pragma unroll
            for (int p=0; p<48; p++){
                float a0, a1; unpack2(acc[p], a0, a1);
                row[(2*p  ) ^ sw] = silu_f(a0)*wc;       // phi[j][c]*w3[c], transposed store
                row[(2*p+1) ^ sw] = silu_f(a1)*wc;
            }
        }
        __syncthreads();
        float v0=0.f, v1=0.f, v2=0.f;
        if (c < NN){
            float s = 0.f;
            for (int k=0; k<HD; k++) s += ms[k*NN + (c ^ ((k&7)<<2))];  // s_j = phi_j @ w3
            float e  = em[(size_t)bi*NN + c];
            float sc = s * e;
            int eo = (bi*NN + c)*3;
            v0 = g_cd[eo+0]*sc; v1 = g_cd[eo+1]*sc; v2 = g_cd[eo+2]*sc;
        }
        __syncthreads();                                 // done reading ms, reuse as reduce buffer
        #pragma unroll
        for (int off=16; off>0; off>>=1){
            v0 += __shfl_down_sync(0xffffffffu, v0, off);
            v1 += __shfl_down_sync(0xffffffffu, v1, off);
            v2 += __shfl_down_sync(0xffffffffu, v2, off);
        }
        if ((c & 31) == 0){
            int w = c >> 5;
            ms[w*4+0] = v0; ms[w*4+1] = v1; ms[w*4+2] = v2;
        }
        __syncthreads();
        if (c < 3){
            float tot = ms[c] + ms[4+c] + ms[8+c] + ms[12+c];
            g_x[bi*3 + c] = (g_x[bi*3 + c] + tot*0.01f) * nm[bi];
        }
    }
}

// ---------------- output head: vel centering + h@W_out ----------------
__global__ void k_out(const float* __restrict__ nm, const float* __restrict__ W_out,
                      const float* __restrict__ b_out, float* __restrict__ out){
    int b = blockIdx.x;
    int n = threadIdx.x;          // 96 threads = 3 warps
    int node = b*NN + n;
    float mask = nm[node];
    float vx = (g_x[node*3+0] - g_x0[node*3+0]) * mask;
    float vy = (g_x[node*3+1] - g_x0[node*3+1]) * mask;
    float vz = (g_x[node*3+2] - g_x0[node*3+2]) * mask;
    float r0 = mask, r1 = vx, r2 = vy, r3 = vz;
    #pragma unroll
    for (int off=16; off>0; off>>=1){
        r0 += __shfl_down_sync(0xffffffffu, r0, off);
        r1 += __shfl_down_sync(0xffffffffu, r1, off);
        r2 += __shfl_down_sync(0xffffffffu, r2, off);
        r3 += __shfl_down_sync(0xffffffffu, r3, off);
    }
    __shared__ float part[3][4];
    int w = n >> 5;
    if ((n & 31) == 0){ part[w][0]=r0; part[w][1]=r1; part[w][2]=r2; part[w][3]=r3; }
    __syncthreads();
    float n_per = part[0][0] + part[1][0] + part[2][0];
    float sx    = part[0][1] + part[1][1] + part[2][1];
    float sy    = part[0][2] + part[1][2] + part[2][2];
    float sz    = part[0][3] + part[1][3] + part[2][3];
    float inv = 1.0f / n_per;
    out[node*9+0] = vx - sx*inv*mask;
    out[node*9+1] = vy - sy*inv*mask;
    out[node*9+2] = vz - sz*inv*mask;
    float acc[6];
    #pragma unroll
    for (int f=0; f<6; f++) acc[f] = b_out[f];
    const float* hrow = g_h + (size_t)node*HD;
    for (int k=0; k<HD; k++){
        float hv = hrow[k];
        #pragma unroll
        for (int f=0; f<6; f++) acc[f] += hv * W_out[k*7 + f];
    }
    #pragma unroll
    for (int f=0; f<6; f++) out[node*9+3+f] = acc[f] * mask;
}

// ---------------- launch ----------------
extern "C" void kernel_launch(void* const* d_in, const int* in_sizes, int n_in,
                              void* d_out, int out_size){
    (void)in_sizes; (void)n_in; (void)out_size;
    const float* xh    = (const float*)d_in[0];
    const float* t     = (const float*)d_in[1];
    const float* nm    = (const float*)d_in[2];
    const float* em    = (const float*)d_in[3];
    const float* W_emb = (const float*)d_in[4];
    const float* b_emb = (const float*)d_in[5];
    const float* gWe1  = (const float*)d_in[6];
    const float* gbe1  = (const float*)d_in[7];
    const float* gWe2  = (const float*)d_in[8];
    const float* gbe2  = (const float*)d_in[9];
    const float* gWn1  = (const float*)d_in[10];
    const float* gbn1  = (const float*)d_in[11];
    const float* gWn2  = (const float*)d_in[12];
    const float* gbn2  = (const float*)d_in[13];
    const float* eWc1  = (const float*)d_in[14];
    const float* ebc1  = (const float*)d_in[15];
    const float* eWc2  = (const float*)d_in[16];
    const float* ebc2  = (const float*)d_in[17];
    const float* eWc3  = (const float*)d_in[18];
    const float* W_out = (const float*)d_in[19];
    const float* b_out = (const float*)d_in[20];
    float* out = (float*)d_out;

    k_prepack<<<(12*HD*HD)/256, 256>>>(gWe2, eWc2);
    k_init<<<BN, HD>>>(xh, t, nm, W_emb, b_emb);
    k_radial<<<BN, NN>>>(0);

    for (int l=0; l<4; l++){
        k_radial<<<BN, NN>>>(1);
        for (int s=0; s<2; s++){
            int g = l*2 + s;
            k_hihj<<<BN/NPB, HD>>>(gWe1 + (size_t)g*258*HD, gbe1 + g*HD);
            k_edge<0><<<BN, HD>>>(gWe1 + (size_t)g*258*HD, gbe2 + g*HD, (const float*)0, em, nm, g);
            k_node<<<BN/NPB, HD>>>(gWn1 + (size_t)g*256*HD, gbn1 + g*HD,
                                   gWn2 + (size_t)g*HD*HD,  gbn2 + g*HD, nm);
        }
        k_hihj<<<BN/NPB, HD>>>(eWc1 + (size_t)l*258*HD, ebc1 + l*HD);
        k_edge<1><<<BN, HD>>>(eWc1 + (size_t)l*258*HD, ebc2 + l*HD, eWc3 + (size_t)l*HD,
                              em, nm, 8 + l);
    }
    k_out<<<BSZ, NN>>>(nm, W_out, b_out, out);
}

// round 2
// speedup vs baseline: 1.0024x; 1.0024x over previous
#include <cuda_runtime.h>

#define BSZ 16
#define NN  96
#define HD  128
#define BN  (BSZ*NN)
#define NPB 8

typedef unsigned long long ull;

// ---------------- scratch (no allocations allowed) ----------------
__device__ float g_h  [BN*HD];
__device__ float g_Hi [BN*HD];
__device__ float g_Hj [BN*HD];
__device__ float g_agg[BN*HD];
__device__ float g_x  [BN*3];
__device__ float g_x0 [BN*3];
__device__ float g_rad[BN*NN];
__device__ float g_d0 [BN*NN];
__device__ float g_cd [BN*NN*3];
__device__ ull   g_W2p[12*HD*HD];   // {w,w}-packed W2 matrices: 8x gWe2 then 4x eWc2

// ---------------- helpers ----------------
__device__ __forceinline__ float silu_f(float x){
    // exact-ish: x * sigmoid(x); MUFU.EX2 + MUFU.RCP, rel err ~1e-6
    float e = __expf(-x);
    return __fdividef(x, 1.0f + e);
}
__device__ __forceinline__ ull pack2(float x, float y){
    ull r; asm("mov.b64 %0, {%1,%2};" : "=l"(r) : "f"(x), "f"(y)); return r;
}
__device__ __forceinline__ void unpack2(ull v, float &x, float &y){
    asm("mov.b64 {%0,%1}, %2;" : "=f"(x), "=f"(y) : "l"(v));
}
__device__ __forceinline__ void ffma2(ull &d, ull a, ull b){
    // packed fp32x2 FMA (Blackwell): d = a*b + d  (2 MACs / instruction)
    asm("fma.rn.f32x2 %0, %1, %2, %0;" : "+l"(d) : "l"(a), "l"(b));
}
union F4U2 { float4 f; ull u[2]; };

// ---------------- prepack W2 matrices into {w,w} u64 ----------------
__global__ void k_prepack(const float* __restrict__ gWe2, const float* __restrict__ eWc2){
    int i = blockIdx.x*blockDim.x + threadIdx.x;
    const int n1 = 8*HD*HD;
    if (i < n1){ float v = gWe2[i];      g_W2p[i] = pack2(v,v); }
    else if (i < 12*HD*HD){ float v = eWc2[i-n1]; g_W2p[i] = pack2(v,v); }
}

// ---------------- init: mask xh, x0/x, h = emb ----------------
__global__ void k_init(const float* __restrict__ xh, const float* __restrict__ t,
                       const float* __restrict__ nm, const float* __restrict__ W_emb,
                       const float* __restrict__ b_emb){
    int n = blockIdx.x; int c = threadIdx.x;
    __shared__ float fs[8];
    float mask = nm[n];
    if (c < 6) fs[c] = xh[n*9 + 3 + c] * mask;
    if (c == 6) fs[6] = t[0];                   // time feature is NOT masked
    if (c < 3){ float v = xh[n*9 + c] * mask; g_x0[n*3+c] = v; g_x[n*3+c] = v; }
    __syncthreads();
    float a = b_emb[c];
    #pragma unroll
    for (int f=0; f<7; f++) a += fs[f] * W_emb[f*HD + c];
    g_h[n*HD + c] = a;
}

// ---------------- radial / d0 / coord_diff ----------------
__global__ void k_radial(int mode){   // mode 0: d0 from x0;  mode 1: radial + coord_diff from x
    int bi = blockIdx.x; int j = threadIdx.x;
    int b = bi / NN;
    const float* X = mode ? g_x : g_x0;
    float xi0 = X[bi*3+0], xi1 = X[bi*3+1], xi2 = X[bi*3+2];
    int nj = b*NN + j;
    float dx = xi0 - X[nj*3+0];
    float dy = xi1 - X[nj*3+1];
    float dz = xi2 - X[nj*3+2];
    float r = dx*dx + dy*dy + dz*dz;
    if (mode){
        g_rad[bi*NN + j] = r;
        float inv = rsqrtf(r + 1e-8f);
        int e = (bi*NN + j)*3;
        g_cd[e+0] = dx*inv; g_cd[e+1] = dy*inv; g_cd[e+2] = dz*inv;
    } else {
        g_d0[bi*NN + j] = r;
    }
}

// ---------------- Hi = h@W1[:128]+b1 ; Hj = h@W1[128:256]  (8 nodes/block) ----------------
__global__ void k_hihj(const float* __restrict__ W1, const float* __restrict__ b1){
    int n0 = blockIdx.x * NPB;
    int c  = threadIdx.x;
    __shared__ float hs[NPB][HD];
    #pragma unroll
    for (int u=0; u<NPB; u++) hs[u][c] = g_h[(n0+u)*HD + c];
    __syncthreads();
    float ai[NPB], aj[NPB];
    float bb = b1[c];
    #pragma unroll
    for (int u=0; u<NPB; u++){ ai[u]=bb; aj[u]=0.f; }
    for (int k=0; k<HD; k++){
        float wi = W1[k*HD + c];
        float wj = W1[(HD+k)*HD + c];
        #pragma unroll
        for (int u=0; u<NPB; u++){ float hv = hs[u][k]; ai[u] += hv*wi; aj[u] += hv*wj; }
    }
    #pragma unroll
    for (int u=0; u<NPB; u++){ g_Hi[(n0+u)*HD+c] = ai[u]; g_Hj[(n0+u)*HD+c] = aj[u]; }
}

// ---------------- node update: u=silu(h@Wn1a + agg@Wn1b + bn1); h=(h+u@Wn2+bn2)*nm ----------------
__global__ void k_node(const float* __restrict__ Wn1, const float* __restrict__ bn1,
                       const float* __restrict__ Wn2, const float* __restrict__ bn2,
                       const float* __restrict__ nm){
    int n0 = blockIdx.x * NPB;
    int c  = threadIdx.x;
    __shared__ float hs[NPB][HD], as[NPB][HD], us[NPB][HD];
    #pragma unroll
    for (int u=0; u<NPB; u++){ hs[u][c] = g_h[(n0+u)*HD+c]; as[u][c] = g_agg[(n0+u)*HD+c]; }
    __syncthreads();
    float acc[NPB];
    float b1v = bn1[c];
    #pragma unroll
    for (int u=0; u<NPB; u++) acc[u] = b1v;
    for (int k=0; k<HD; k++){
        float w1 = Wn1[k*HD + c], w2 = Wn1[(HD+k)*HD + c];
        #pragma unroll
        for (int u=0; u<NPB; u++) acc[u] += hs[u][k]*w1 + as[u][k]*w2;
    }
    #pragma unroll
    for (int u=0; u<NPB; u++) us[u][c] = silu_f(acc[u]);
    __syncthreads();
    float b2v = bn2[c];
    #pragma unroll
    for (int u=0; u<NPB; u++) acc[u] = b2v;
    for (int k=0; k<HD; k++){
        float w = Wn2[k*HD + c];
        #pragma unroll
        for (int u=0; u<NPB; u++) acc[u] += us[u][k]*w;
    }
    #pragma unroll
    for (int u=0; u<NPB; u++) g_h[(n0+u)*HD+c] = (hs[u][c] + acc[u]) * nm[n0+u];
}

// ---------------- edge MLP: one block per (b,i); 48 packed-f32x2 accumulators ----------------
// COORD=0: agg[b,i,c] = sum_j silu(out)*em / 100
// COORD=1: x[b,i] = (x[b,i] + sum_j cd*(phi@w3)*em / 100)*nm
template<int COORD>
__global__ void __launch_bounds__(128,3) k_edge(const float* __restrict__ W1,
        const float* __restrict__ b2, const float* __restrict__ w3,
        const float* __restrict__ em, const float* __restrict__ nm, int widx){
    __shared__ float ms[HD*NN];   // [k][j], XOR-swizzled: word = k*96 + (j ^ ((k&7)<<2)); 48KB
    int bi = blockIdx.x;
    int b  = bi / NN;
    int c  = threadIdx.x;

    // ---- stage 1: m[c][j] = silu(Hi[i,c] + Hj[j,c] + radial*w0 + d0*w1)  (b1 folded in Hi)
    {
        float hi = g_Hi[bi*HD + c];
        float w0 = W1[256*HD + c];
        float w1 = W1[257*HD + c];
        const float* Hjb    = g_Hj + (size_t)b*NN*HD + c;
        const float* radRow = g_rad + bi*NN;
        const float* d0Row  = g_d0  + bi*NN;
        int sw = (c & 7) << 2;
        float* mrow = ms + c*NN;
        for (int j0=0; j0<NN; j0+=4){
            float4 mv;
            mv.x = silu_f(hi + Hjb[(j0+0)*HD] + radRow[j0+0]*w0 + d0Row[j0+0]*w1);
            mv.y = silu_f(hi + Hjb[(j0+1)*HD] + radRow[j0+1]*w0 + d0Row[j0+1]*w1);
            mv.z = silu_f(hi + Hjb[(j0+2)*HD] + radRow[j0+2]*w0 + d0Row[j0+2]*w1);
            mv.w = silu_f(hi + Hjb[(j0+3)*HD] + radRow[j0+3]*w0 + d0Row[j0+3]*w1);
            *reinterpret_cast<float4*>(mrow + (j0 ^ sw)) = mv;
        }
    }
    __syncthreads();

    // ---- stage 2: out[j][c] = sum_k m[k][j] * W2[k][c] + b2[c], all 96 j live (48 f32x2 pairs)
    ull acc[48];
    {
        float bb = b2[c];
        ull bp = pack2(bb, bb);
        #pragma unroll
        for (int p=0; p<48; p++) acc[p] = bp;
    }
    const ull* Wp = g_W2p + (size_t)widx*HD*HD + c;
    const float* mrow = ms;
    for (int kk=0; kk<16; kk++){
        #pragma unroll
        for (int r=0; r<8; r++){          // r = k&7 known at compile time -> immediate LDS offsets
            ull w = *Wp; Wp += HD;
            #pragma unroll
            for (int q=0; q<24; q++){
                F4U2 v;
                v.f = *reinterpret_cast<const float4*>(mrow + ((q*4) ^ (r*4)));
                ffma2(acc[2*q  ], v.u[0], w);
                ffma2(acc[2*q+1], v.u[1], w);
            }
            mrow += NN;
        }
    }

    if (COORD == 0){
        float s = 0.f;
        const float* emrow = em + (size_t)bi*NN;
        #pragma unroll
        for (int p=0; p<48; p++){
            float a0, a1; unpack2(acc[p], a0, a1);      // acc[p] holds j = 2p, 2p+1
            s += silu_f(a0)*emrow[2*p] + silu_f(a1)*emrow[2*p+1];
        }
        g_agg[bi*HD + c] = s * 0.01f;
    } else {
        float wc = w3[c];
        __syncthreads();                                 // everyone done reading ms
        {
            int sw = (c & 7) << 2;
            float* row = ms + c*NN;
            #pragma unroll
            for (int p=0; p<48; p++){
                float a0, a1; unpack2(acc[p], a0, a1);
                row[(2*p  ) ^ sw] = silu_f(a0)*wc;       // phi[j][c]*w3[c], transposed store
                row[(2*p+1) ^ sw] = silu_f(a1)*wc;
            }
        }
        __syncthreads();
        float v0=0.f, v1=0.f, v2=0.f;
        if (c < NN){
            float s = 0.f;
            for (int k=0; k<HD; k++) s += ms[k*NN + (c ^ ((k&7)<<2))];  // s_j = phi_j @ w3
            float e  = em[(size_t)bi*NN + c];
            float sc = s * e;
            int eo = (bi*NN + c)*3;
            v0 = g_cd[eo+0]*sc; v1 = g_cd[eo+1]*sc; v2 = g_cd[eo+2]*sc;
        }
        __syncthreads();                                 // done reading ms, reuse as reduce buffer
        #pragma unroll
        for (int off=16; off>0; off>>=1){
            v0 += __shfl_down_sync(0xffffffffu, v0, off);
            v1 += __shfl_down_sync(0xffffffffu, v1, off);
            v2 += __shfl_down_sync(0xffffffffu, v2, off);
        }
        if ((c & 31) == 0){
            int w = c >> 5;
            ms[w*4+0] = v0; ms[w*4+1] = v1; ms[w*4+2] = v2;
        }
        __syncthreads();
        if (c < 3){
            float tot = ms[c] + ms[4+c] + ms[8+c] + ms[12+c];
            g_x[bi*3 + c] = (g_x[bi*3 + c] + tot*0.01f) * nm[bi];
        }
    }
}

// ---------------- output head: vel centering + h@W_out ----------------
__global__ void k_out(const float* __restrict__ nm, const float* __restrict__ W_out,
                      const float* __restrict__ b_out, float* __restrict__ out){
    int b = blockIdx.x;
    int n = threadIdx.x;          // 96 threads = 3 warps
    int node = b*NN + n;
    float mask = nm[node];
    float vx = (g_x[node*3+0] - g_x0[node*3+0]) * mask;
    float vy = (g_x[node*3+1] - g_x0[node*3+1]) * mask;
    float vz = (g_x[node*3+2] - g_x0[node*3+2]) * mask;
    float r0 = mask, r1 = vx, r2 = vy, r3 = vz;
    #pragma unroll
    for (int off=16; off>0; off>>=1){
        r0 += __shfl_down_sync(0xffffffffu, r0, off);
        r1 += __shfl_down_sync(0xffffffffu, r1, off);
        r2 += __shfl_down_sync(0xffffffffu, r2, off);
        r3 += __shfl_down_sync(0xffffffffu, r3, off);
    }
    __shared__ float part[3][4];
    int w = n >> 5;
    if ((n & 31) == 0){ part[w][0]=r0; part[w][1]=r1; part[w][2]=r2; part[w][3]=r3; }
    __syncthreads();
    float n_per = part[0][0] + part[1][0] + part[2][0];
    float sx    = part[0][1] + part[1][1] + part[2][1];
    float sy    = part[0][2] + part[1][2] + part[2][2];
    float sz    = part[0][3] + part[1][3] + part[2][3];
    float inv = 1.0f / n_per;
    out[node*9+0] = vx - sx*inv*mask;
    out[node*9+1] = vy - sy*inv*mask;
    out[node*9+2] = vz - sz*inv*mask;
    float acc[6];
    #pragma unroll
    for (int f=0; f<6; f++) acc[f] = b_out[f];
    const float* hrow = g_h + (size_t)node*HD;
    for (int k=0; k<HD; k++){
        float hv = hrow[k];
        #pragma unroll
        for (int f=0; f<6; f++) acc[f] += hv * W_out[k*7 + f];
    }
    #pragma unroll
    for (int f=0; f<6; f++) out[node*9+3+f] = acc[f] * mask;
}

// ---------------- launch ----------------
extern "C" void kernel_launch(void* const* d_in, const int* in_sizes, int n_in,
                              void* d_out, int out_size){
    (void)in_sizes; (void)n_in; (void)out_size;
    const float* xh    = (const float*)d_in[0];
    const float* t     = (const float*)d_in[1];
    const float* nm    = (const float*)d_in[2];
    const float* em    = (const float*)d_in[3];
    const float* W_emb = (const float*)d_in[4];
    const float* b_emb = (const float*)d_in[5];
    const float* gWe1  = (const float*)d_in[6];
    const float* gbe1  = (const float*)d_in[7];
    const float* gWe2  = (const float*)d_in[8];
    const float* gbe2  = (const float*)d_in[9];
    const float* gWn1  = (const float*)d_in[10];
    const float* gbn1  = (const float*)d_in[11];
    const float* gWn2  = (const float*)d_in[12];
    const float* gbn2  = (const float*)d_in[13];
    const float* eWc1  = (const float*)d_in[14];
    const float* ebc1  = (const float*)d_in[15];
    const float* eWc2  = (const float*)d_in[16];
    const float* ebc2  = (const float*)d_in[17];
    const float* eWc3  = (const float*)d_in[18];
    const float* W_out = (const float*)d_in[19];
    const float* b_out = (const float*)d_in[20];
    float* out = (float*)d_out;

    k_prepack<<<(12*HD*HD)/256, 256>>>(gWe2, eWc2);
    k_init<<<BN, HD>>>(xh, t, nm, W_emb, b_emb);
    k_radial<<<BN, NN>>>(0);

    for (int l=0; l<4; l++){
        k_radial<<<BN, NN>>>(1);
        for (int s=0; s<2; s++){
            int g = l*2 + s;
            k_hihj<<<BN/NPB, HD>>>(gWe1 + (size_t)g*258*HD, gbe1 + g*HD);
            k_edge<0><<<BN, HD>>>(gWe1 + (size_t)g*258*HD, gbe2 + g*HD, (const float*)0, em, nm, g);
            k_node<<<BN/NPB, HD>>>(gWn1 + (size_t)g*256*HD, gbn1 + g*HD,
                                   gWn2 + (size_t)g*HD*HD,  gbn2 + g*HD, nm);
        }
        k_hihj<<<BN/NPB, HD>>>(eWc1 + (size_t)l*258*HD, ebc1 + l*HD);
        k_edge<1><<<BN, HD>>>(eWc1 + (size_t)l*258*HD, ebc2 + l*HD, eWc3 + (size_t)l*HD,
                              em, nm, 8 + l);
    }
    k_out<<<BSZ, NN>>>(nm, W_out, b_out, out);
}

// round 4
// speedup vs baseline: 1.2172x; 1.2143x over previous
#include <cuda_runtime.h>
#include <cuda_bf16.h>
#include <mma.h>
#include <cstdint>

using namespace nvcuda;

#define BSZ 16
#define NN  96
#define HD  128
#define BN  (BSZ*NN)
#define NPB 8

#define LDAB 136          // bf16 leading dim for m / W2 tiles
#define LDO  132          // fp32 leading dim for out tile

// ---- dynamic smem layout (bytes) ----
#define W2HI  0           // 128*136*2 = 34816
#define W2LO  34816       // 34816
#define MHI   69632       // 96*136*2 = 26112
#define MLO   95744       // 26112 -> 121856
#define OUTO  69632       // fp32 out[96][132] = 50688, reuses MHI/MLO after MMA
#define RSO   121856      // 96 f
#define DSO   122240
#define EMO   122624
#define B2O   123008      // 128 f
#define W3O   123520      // 128 f
#define PARTO 124032      // 2*128 f = 1024
#define SMEMB 125184

// ---------------- scratch ----------------
__device__ float g_h  [BN*HD];
__device__ float g_Hi [BN*HD];
__device__ float g_Hj [BN*HD];
__device__ float g_agg[BN*HD];
__device__ float g_x  [BN*3];
__device__ float g_x0 [BN*3];
__device__ float g_rad[BN*NN];
__device__ float g_d0 [BN*NN];
__device__ float g_cd [BN*NN*3];

__device__ __forceinline__ float silu_f(float x){
    float e = __expf(-x);
    return __fdividef(x, 1.0f + e);
}

// ---------------- init ----------------
__global__ void k_init(const float* __restrict__ xh, const float* __restrict__ t,
                       const float* __restrict__ nm, const float* __restrict__ W_emb,
                       const float* __restrict__ b_emb){
    int n = blockIdx.x; int c = threadIdx.x;
    __shared__ float fs[8];
    float mask = nm[n];
    if (c < 6) fs[c] = xh[n*9 + 3 + c] * mask;
    if (c == 6) fs[6] = t[0];
    if (c < 3){ float v = xh[n*9 + c] * mask; g_x0[n*3+c] = v; g_x[n*3+c] = v; }
    __syncthreads();
    float a = b_emb[c];
    #pragma unroll
    for (int f=0; f<7; f++) a += fs[f] * W_emb[f*HD + c];
    g_h[n*HD + c] = a;
}

// ---------------- radial ----------------
__global__ void k_radial(int mode){
    int bi = blockIdx.x; int j = threadIdx.x;
    int b = bi / NN;
    const float* X = mode ? g_x : g_x0;
    float xi0 = X[bi*3+0], xi1 = X[bi*3+1], xi2 = X[bi*3+2];
    int nj = b*NN + j;
    float dx = xi0 - X[nj*3+0];
    float dy = xi1 - X[nj*3+1];
    float dz = xi2 - X[nj*3+2];
    float r = dx*dx + dy*dy + dz*dz;
    if (mode){
        g_rad[bi*NN + j] = r;
        float inv = rsqrtf(r + 1e-8f);
        int e = (bi*NN + j)*3;
        g_cd[e+0] = dx*inv; g_cd[e+1] = dy*inv; g_cd[e+2] = dz*inv;
    } else {
        g_d0[bi*NN + j] = r;
    }
}

// ---------------- Hi/Hj ----------------
__global__ void k_hihj(const float* __restrict__ W1, const float* __restrict__ b1){
    int n0 = blockIdx.x * NPB;
    int c  = threadIdx.x;
    __shared__ float hs[NPB][HD];
    #pragma unroll
    for (int u=0; u<NPB; u++) hs[u][c] = g_h[(n0+u)*HD + c];
    __syncthreads();
    float ai[NPB], aj[NPB];
    float bb = b1[c];
    #pragma unroll
    for (int u=0; u<NPB; u++){ ai[u]=bb; aj[u]=0.f; }
    for (int k=0; k<HD; k++){
        float wi = W1[k*HD + c];
        float wj = W1[(HD+k)*HD + c];
        #pragma unroll
        for (int u=0; u<NPB; u++){ float hv = hs[u][k]; ai[u] += hv*wi; aj[u] += hv*wj; }
    }
    #pragma unroll
    for (int u=0; u<NPB; u++){ g_Hi[(n0+u)*HD+c] = ai[u]; g_Hj[(n0+u)*HD+c] = aj[u]; }
}

// ---------------- node update ----------------
__global__ void k_node(const float* __restrict__ Wn1, const float* __restrict__ bn1,
                       const float* __restrict__ Wn2, const float* __restrict__ bn2,
                       const float* __restrict__ nm){
    int n0 = blockIdx.x * NPB;
    int c  = threadIdx.x;
    __shared__ float hs[NPB][HD], as[NPB][HD], us[NPB][HD];
    #pragma unroll
    for (int u=0; u<NPB; u++){ hs[u][c] = g_h[(n0+u)*HD+c]; as[u][c] = g_agg[(n0+u)*HD+c]; }
    __syncthreads();
    float acc[NPB];
    float b1v = bn1[c];
    #pragma unroll
    for (int u=0; u<NPB; u++) acc[u] = b1v;
    for (int k=0; k<HD; k++){
        float w1 = Wn1[k*HD + c], w2 = Wn1[(HD+k)*HD + c];
        #pragma unroll
        for (int u=0; u<NPB; u++) acc[u] += hs[u][k]*w1 + as[u][k]*w2;
    }
    #pragma unroll
    for (int u=0; u<NPB; u++) us[u][c] = silu_f(acc[u]);
    __syncthreads();
    float b2v = bn2[c];
    #pragma unroll
    for (int u=0; u<NPB; u++) acc[u] = b2v;
    for (int k=0; k<HD; k++){
        float w = Wn2[k*HD + c];
        #pragma unroll
        for (int u=0; u<NPB; u++) acc[u] += us[u][k]*w;
    }
    #pragma unroll
    for (int u=0; u<NPB; u++) g_h[(n0+u)*HD+c] = (hs[u][c] + acc[u]) * nm[n0+u];
}

// ---------------- WMMA edge MLP (persistent, 256 thr, bf16 hi/lo 3-GEMM) ----------------
// out[j(96), c(128)] = sum_k m[j,k] * W2[k,c];  A=m (row-major), B=W2 (row-major K x N)
template<int COORD>
__global__ void __launch_bounds__(256,1) k_edgeW(const float* __restrict__ W1,
        const float* __restrict__ W2, const float* __restrict__ b2,
        const float* __restrict__ w3, const float* __restrict__ em,
        const float* __restrict__ nm){
    extern __shared__ char sm[];
    __nv_bfloat16* w2h = (__nv_bfloat16*)(sm + W2HI);
    __nv_bfloat16* w2l = (__nv_bfloat16*)(sm + W2LO);
    __nv_bfloat16* mh  = (__nv_bfloat16*)(sm + MHI);
    __nv_bfloat16* ml  = (__nv_bfloat16*)(sm + MLO);
    float* outp = (float*)(sm + OUTO);
    float* rs   = (float*)(sm + RSO);
    float* ds   = (float*)(sm + DSO);
    float* ems  = (float*)(sm + EMO);
    float* b2s  = (float*)(sm + B2O);
    float* w3s  = (float*)(sm + W3O);
    float* part = (float*)(sm + PARTO);

    int tid = threadIdx.x;
    int wid = tid >> 5;
    int c   = tid & 127;          // channel for stage1/epilogue
    int jg  = tid >> 7;           // 0/1: j-half

    // ---- per-pass setup: W2 hi/lo split, bias/w3 ----
    for (int idx = tid; idx < HD*HD; idx += 256){
        int k = idx >> 7, cc = idx & 127;
        float v = W2[idx];
        __nv_bfloat16 h16 = __float2bfloat16(v);
        __nv_bfloat16 l16 = __float2bfloat16(v - __bfloat162float(h16));
        w2h[k*LDAB + cc] = h16;
        w2l[k*LDAB + cc] = l16;
    }
    if (tid < 128){
        b2s[tid] = b2[tid];
        w3s[tid] = COORD ? w3[tid] : 0.f;
    }
    float w0 = W1[(2*HD)  *HD + c];
    float w1 = W1[(2*HD+1)*HD + c];
    float b2c = b2[c];

    for (int bi = blockIdx.x; bi < BN; bi += gridDim.x){
        int b = bi / NN;
        __syncthreads();   // previous tile's epilogue fully done (outp/ems reads)

        if (tid < NN){
            rs[tid]  = g_rad[bi*NN + tid];
            ds[tid]  = g_d0 [bi*NN + tid];
            ems[tid] = em[(size_t)bi*NN + tid];
        }
        float hiv = g_Hi[bi*HD + c];
        __syncthreads();   // rs/ds visible

        // ---- stage 1: m[j][c] = silu(Hi + Hj + rad*w0 + d0*w1) -> bf16 hi/lo ----
        {
            const float* Hjb = g_Hj + (size_t)b*NN*HD + c;
            int j0 = jg*48, j1 = j0+48;
            for (int j=j0; j<j1; j++){
                float v = silu_f(hiv + Hjb[(size_t)j*HD] + rs[j]*w0 + ds[j]*w1);
                __nv_bfloat16 h16 = __float2bfloat16(v);
                __nv_bfloat16 l16 = __float2bfloat16(v - __bfloat162float(h16));
                mh[j*LDAB + c] = h16;
                ml[j*LDAB + c] = l16;
            }
        }
        __syncthreads();

        // ---- MMA: warp wid covers columns [wid*16, wid*16+16) ----
        {
            int cw = wid * 16;
            wmma::fragment<wmma::accumulator,16,16,16,float> acc[6];
            #pragma unroll
            for (int mi=0; mi<6; mi++) wmma::fill_fragment(acc[mi], 0.0f);
            #pragma unroll
            for (int s=0; s<8; s++){
                wmma::fragment<wmma::matrix_a,16,16,16,__nv_bfloat16,wmma::row_major> ah[6], al[6];
                wmma::fragment<wmma::matrix_b,16,16,16,__nv_bfloat16,wmma::row_major> bh, bl;
                #pragma unroll
                for (int mi=0; mi<6; mi++){
                    wmma::load_matrix_sync(ah[mi], mh + mi*16*LDAB + s*16, LDAB);
                    wmma::load_matrix_sync(al[mi], ml + mi*16*LDAB + s*16, LDAB);
                }
                wmma::load_matrix_sync(bh, w2h + s*16*LDAB + cw, LDAB);
                wmma::load_matrix_sync(bl, w2l + s*16*LDAB + cw, LDAB);
                #pragma unroll
                for (int mi=0; mi<6; mi++){
                    wmma::mma_sync(acc[mi], ah[mi], bh, acc[mi]);
                    wmma::mma_sync(acc[mi], ah[mi], bl, acc[mi]);
                    wmma::mma_sync(acc[mi], al[mi], bh, acc[mi]);
                }
            }
            __syncthreads();   // all warps done reading mh/ml before overwrite
            #pragma unroll
            for (int mi=0; mi<6; mi++)
                wmma::store_matrix_sync(outp + mi*16*LDO + cw, acc[mi], LDO, wmma::mem_row_major);
        }
        __syncthreads();

        // ---- epilogue ----
        if (COORD == 0){
            float s = 0.f;
            int j0 = jg*48, j1 = j0+48;
            for (int j=j0; j<j1; j++)
                s += silu_f(outp[j*LDO + c] + b2c) * ems[j];
            part[jg*128 + c] = s;
            __syncthreads();
            if (tid < 128)
                g_agg[bi*HD + tid] = (part[tid] + part[128 + tid]) * 0.01f;
        } else {
            float v0=0.f, v1=0.f, v2=0.f;
            if (tid < NN){
                int j = tid;
                float s = 0.f;
                const float* row = outp + j*LDO;
                for (int k=0; k<HD; k++)
                    s += silu_f(row[k] + b2s[k]) * w3s[k];
                float sc = s * ems[j];
                int eo = (bi*NN + j)*3;
                v0 = g_cd[eo+0]*sc; v1 = g_cd[eo+1]*sc; v2 = g_cd[eo+2]*sc;
            }
            #pragma unroll
            for (int off=16; off>0; off>>=1){
                v0 += __shfl_down_sync(0xffffffffu, v0, off);
                v1 += __shfl_down_sync(0xffffffffu, v1, off);
                v2 += __shfl_down_sync(0xffffffffu, v2, off);
            }
            if (tid < NN && (tid & 31) == 0){
                int w = tid >> 5;
                part[w*4+0] = v0; part[w*4+1] = v1; part[w*4+2] = v2;
            }
            __syncthreads();
            if (tid < 3){
                float tot = part[tid] + part[4+tid] + part[8+tid];
                g_x[bi*3 + tid] = (g_x[bi*3 + tid] + tot*0.01f) * nm[bi];
            }
        }
    }
}

// ---------------- output head ----------------
__global__ void k_out(const float* __restrict__ nm, const float* __restrict__ W_out,
                      const float* __restrict__ b_out, float* __restrict__ out){
    int b = blockIdx.x;
    int n = threadIdx.x;
    int node = b*NN + n;
    float mask = nm[node];
    float vx = (g_x[node*3+0] - g_x0[node*3+0]) * mask;
    float vy = (g_x[node*3+1] - g_x0[node*3+1]) * mask;
    float vz = (g_x[node*3+2] - g_x0[node*3+2]) * mask;
    float r0 = mask, r1 = vx, r2 = vy, r3 = vz;
    #pragma unroll
    for (int off=16; off>0; off>>=1){
        r0 += __shfl_down_sync(0xffffffffu, r0, off);
        r1 += __shfl_down_sync(0xffffffffu, r1, off);
        r2 += __shfl_down_sync(0xffffffffu, r2, off);
        r3 += __shfl_down_sync(0xffffffffu, r3, off);
    }
    __shared__ float part[3][4];
    int w = n >> 5;
    if ((n & 31) == 0){ part[w][0]=r0; part[w][1]=r1; part[w][2]=r2; part[w][3]=r3; }
    __syncthreads();
    float n_per = part[0][0] + part[1][0] + part[2][0];
    float sx    = part[0][1] + part[1][1] + part[2][1];
    float sy    = part[0][2] + part[1][2] + part[2][2];
    float sz    = part[0][3] + part[1][3] + part[2][3];
    float inv = 1.0f / n_per;
    out[node*9+0] = vx - sx*inv*mask;
    out[node*9+1] = vy - sy*inv*mask;
    out[node*9+2] = vz - sz*inv*mask;
    float acc[6];
    #pragma unroll
    for (int f=0; f<6; f++) acc[f] = b_out[f];
    const float* hrow = g_h + (size_t)node*HD;
    for (int k=0; k<HD; k++){
        float hv = hrow[k];
        #pragma unroll
        for (int f=0; f<6; f++) acc[f] += hv * W_out[k*7 + f];
    }
    #pragma unroll
    for (int f=0; f<6; f++) out[node*9+3+f] = acc[f] * mask;
}

// ---------------- launch ----------------
extern "C" void kernel_launch(void* const* d_in, const int* in_sizes, int n_in,
                              void* d_out, int out_size){
    (void)in_sizes; (void)n_in; (void)out_size;
    const float* xh    = (const float*)d_in[0];
    const float* t     = (const float*)d_in[1];
    const float* nm    = (const float*)d_in[2];
    const float* em    = (const float*)d_in[3];
    const float* W_emb = (const float*)d_in[4];
    const float* b_emb = (const float*)d_in[5];
    const float* gWe1  = (const float*)d_in[6];
    const float* gbe1  = (const float*)d_in[7];
    const float* gWe2  = (const float*)d_in[8];
    const float* gbe2  = (const float*)d_in[9];
    const float* gWn1  = (const float*)d_in[10];
    const float* gbn1  = (const float*)d_in[11];
    const float* gWn2  = (const float*)d_in[12];
    const float* gbn2  = (const float*)d_in[13];
    const float* eWc1  = (const float*)d_in[14];
    const float* ebc1  = (const float*)d_in[15];
    const float* eWc2  = (const float*)d_in[16];
    const float* ebc2  = (const float*)d_in[17];
    const float* eWc3  = (const float*)d_in[18];
    const float* W_out = (const float*)d_in[19];
    const float* b_out = (const float*)d_in[20];
    float* out = (float*)d_out;

    cudaFuncSetAttribute(k_edgeW<0>, cudaFuncAttributeMaxDynamicSharedMemorySize, SMEMB);
    cudaFuncSetAttribute(k_edgeW<1>, cudaFuncAttributeMaxDynamicSharedMemorySize, SMEMB);

    k_init<<<BN, HD>>>(xh, t, nm, W_emb, b_emb);
    k_radial<<<BN, NN>>>(0);

    for (int l=0; l<4; l++){
        k_radial<<<BN, NN>>>(1);
        for (int s=0; s<2; s++){
            int g = l*2 + s;
            k_hihj<<<BN/NPB, HD>>>(gWe1 + (size_t)g*258*HD, gbe1 + g*HD);
            k_edgeW<0><<<148, 256, SMEMB>>>(gWe1 + (size_t)g*258*HD, gWe2 + (size_t)g*HD*HD,
                                            gbe2 + g*HD, (const float*)0, em, nm);
            k_node<<<BN/NPB, HD>>>(gWn1 + (size_t)g*256*HD, gbn1 + g*HD,
                                   gWn2 + (size_t)g*HD*HD,  gbn2 + g*HD, nm);
        }
        k_hihj<<<BN/NPB, HD>>>(eWc1 + (size_t)l*258*HD, ebc1 + l*HD);
        k_edgeW<1><<<148, 256, SMEMB>>>(eWc1 + (size_t)l*258*HD, eWc2 + (size_t)l*HD*HD,
                                        ebc2 + l*HD, eWc3 + (size_t)l*HD, em, nm);
    }
    k_out<<<BSZ, NN>>>(nm, W_out, b_out, out);
}

// round 5
// speedup vs baseline: 1.2953x; 1.0641x over previous
#include <cuda_runtime.h>
#include <cuda_bf16.h>
#include <mma.h>
#include <cstdint>

using namespace nvcuda;

#define BSZ 16
#define NN  96
#define HD  128
#define BN  (BSZ*NN)
#define NPB 4

#define LDAB 136          // bf16 leading dim for m / W2 tiles
#define LDO  132          // fp32 leading dim for out tile

// ---- dynamic smem layout (bytes) ----
#define W2HI  0           // 128*136*2 = 34816
#define W2LO  34816
#define MHI   69632       // 96*136*2 = 26112
#define MLO   95744
#define OUTO  121856      // fp32 out[96][132] = 50688 (no alias)
#define RSO   172544
#define DSO   172928
#define EMO   173312
#define B2O   173696
#define W3O   174208
#define PARTO 174720      // 1024 B
#define SMEMB 175872

// ---------------- scratch ----------------
__device__ float g_h  [BN*HD];
__device__ float g_Hi [BN*HD];
__device__ float g_Hj [BN*HD];
__device__ float g_agg[BN*HD];
__device__ float g_x  [BN*3];
__device__ float g_x0 [BN*3];
__device__ float g_rad[BN*NN];
__device__ float g_d0 [BN*NN];
__device__ float g_cd [BN*NN*3];

__device__ __forceinline__ float silu_f(float x){
    float e = __expf(-x);
    return __fdividef(x, 1.0f + e);
}

// ---------------- init ----------------
__global__ void k_init(const float* __restrict__ xh, const float* __restrict__ t,
                       const float* __restrict__ nm, const float* __restrict__ W_emb,
                       const float* __restrict__ b_emb){
    int n = blockIdx.x; int c = threadIdx.x;
    __shared__ float fs[8];
    float mask = nm[n];
    if (c < 6) fs[c] = xh[n*9 + 3 + c] * mask;
    if (c == 6) fs[6] = t[0];
    if (c < 3){ float v = xh[n*9 + c] * mask; g_x0[n*3+c] = v; g_x[n*3+c] = v; }
    __syncthreads();
    float a = b_emb[c];
    #pragma unroll
    for (int f=0; f<7; f++) a += fs[f] * W_emb[f*HD + c];
    g_h[n*HD + c] = a;
}

// ---------------- radial ----------------
__global__ void k_radial(int mode){
    int bi = blockIdx.x; int j = threadIdx.x;
    int b = bi / NN;
    const float* X = mode ? g_x : g_x0;
    float xi0 = X[bi*3+0], xi1 = X[bi*3+1], xi2 = X[bi*3+2];
    int nj = b*NN + j;
    float dx = xi0 - X[nj*3+0];
    float dy = xi1 - X[nj*3+1];
    float dz = xi2 - X[nj*3+2];
    float r = dx*dx + dy*dy + dz*dz;
    if (mode){
        g_rad[bi*NN + j] = r;
        float inv = rsqrtf(r + 1e-8f);
        int e = (bi*NN + j)*3;
        g_cd[e+0] = dx*inv; g_cd[e+1] = dy*inv; g_cd[e+2] = dz*inv;
    } else {
        g_d0[bi*NN + j] = r;
    }
}

// ---------------- Hi/Hj: 4 nodes/block, 256 threads (2 nodes/thread) ----------------
__global__ void __launch_bounds__(256) k_hihj(const float* __restrict__ W1, const float* __restrict__ b1){
    int n0 = blockIdx.x * NPB;
    int tid = threadIdx.x;
    int c = tid & 127;
    int half = tid >> 7;            // 0/1 -> nodes {0,1} or {2,3}
    __shared__ float hs[NPB][HD];
    if (half == 0){
        hs[0][c] = g_h[(n0+0)*HD + c];
        hs[1][c] = g_h[(n0+1)*HD + c];
    } else {
        hs[2][c] = g_h[(n0+2)*HD + c];
        hs[3][c] = g_h[(n0+3)*HD + c];
    }
    __syncthreads();
    int u0 = half*2;
    float bb = b1[c];
    float ai0=bb, ai1=bb, aj0=0.f, aj1=0.f;
    #pragma unroll 4
    for (int k=0; k<HD; k++){
        float wi = W1[k*HD + c];
        float wj = W1[(HD+k)*HD + c];
        float h0 = hs[u0][k], h1 = hs[u0+1][k];
        ai0 += h0*wi; aj0 += h0*wj;
        ai1 += h1*wi; aj1 += h1*wj;
    }
    g_Hi[(n0+u0  )*HD+c] = ai0; g_Hj[(n0+u0  )*HD+c] = aj0;
    g_Hi[(n0+u0+1)*HD+c] = ai1; g_Hj[(n0+u0+1)*HD+c] = aj1;
}

// ---------------- node update: 4 nodes/block, 256 threads ----------------
__global__ void __launch_bounds__(256) k_node(const float* __restrict__ Wn1, const float* __restrict__ bn1,
                       const float* __restrict__ Wn2, const float* __restrict__ bn2,
                       const float* __restrict__ nm){
    int n0 = blockIdx.x * NPB;
    int tid = threadIdx.x;
    int c = tid & 127;
    int half = tid >> 7;
    int u0 = half*2;
    __shared__ float hs[NPB][HD], as[NPB][HD], us[NPB][HD];
    hs[u0  ][c] = g_h[(n0+u0  )*HD+c]; as[u0  ][c] = g_agg[(n0+u0  )*HD+c];
    hs[u0+1][c] = g_h[(n0+u0+1)*HD+c]; as[u0+1][c] = g_agg[(n0+u0+1)*HD+c];
    __syncthreads();
    float b1v = bn1[c];
    float a0 = b1v, a1 = b1v;
    #pragma unroll 4
    for (int k=0; k<HD; k++){
        float w1 = Wn1[k*HD + c], w2 = Wn1[(HD+k)*HD + c];
        a0 += hs[u0  ][k]*w1 + as[u0  ][k]*w2;
        a1 += hs[u0+1][k]*w1 + as[u0+1][k]*w2;
    }
    us[u0  ][c] = silu_f(a0);
    us[u0+1][c] = silu_f(a1);
    __syncthreads();
    float b2v = bn2[c];
    a0 = b2v; a1 = b2v;
    #pragma unroll 4
    for (int k=0; k<HD; k++){
        float w = Wn2[k*HD + c];
        a0 += us[u0  ][k]*w;
        a1 += us[u0+1][k]*w;
    }
    g_h[(n0+u0  )*HD+c] = (hs[u0  ][c] + a0) * nm[n0+u0];
    g_h[(n0+u0+1)*HD+c] = (hs[u0+1][c] + a1) * nm[n0+u0+1];
}

// ---------------- WMMA edge MLP (persistent, 256 thr, 2x4 warp tiling) ----------------
template<int COORD>
__global__ void __launch_bounds__(256,1) k_edgeW(const float* __restrict__ W1,
        const float* __restrict__ W2, const float* __restrict__ b2,
        const float* __restrict__ w3, const float* __restrict__ em,
        const float* __restrict__ nm){
    extern __shared__ char sm[];
    __nv_bfloat16* w2h = (__nv_bfloat16*)(sm + W2HI);
    __nv_bfloat16* w2l = (__nv_bfloat16*)(sm + W2LO);
    __nv_bfloat16* mh  = (__nv_bfloat16*)(sm + MHI);
    __nv_bfloat16* ml  = (__nv_bfloat16*)(sm + MLO);
    float* outp = (float*)(sm + OUTO);
    float* rs   = (float*)(sm + RSO);
    float* ds   = (float*)(sm + DSO);
    float* ems  = (float*)(sm + EMO);
    float* b2s  = (float*)(sm + B2O);
    float* w3s  = (float*)(sm + W3O);
    float* part = (float*)(sm + PARTO);

    int tid = threadIdx.x;
    int wid = tid >> 5;
    int mw  = wid >> 2;           // 0/1: M(j) group of 48
    int nw  = wid & 3;            // 0..3: N(c) group of 32
    int c   = tid & 127;
    int jg  = tid >> 7;

    // ---- per-pass setup ----
    for (int idx = tid; idx < HD*HD; idx += 256){
        int k = idx >> 7, cc = idx & 127;
        float v = W2[idx];
        __nv_bfloat16 h16 = __float2bfloat16(v);
        __nv_bfloat16 l16 = __float2bfloat16(v - __bfloat162float(h16));
        w2h[k*LDAB + cc] = h16;
        w2l[k*LDAB + cc] = l16;
    }
    if (tid < 128){
        b2s[tid] = b2[tid];
        w3s[tid] = COORD ? w3[tid] : 0.f;
    }
    float w0 = W1[(2*HD)  *HD + c];
    float w1 = W1[(2*HD+1)*HD + c];
    float b2c = b2[c];

    for (int bi = blockIdx.x; bi < BN; bi += gridDim.x){
        int b = bi / NN;
        __syncthreads();   // prior epilogue reads of ems/outp complete

        if (tid < NN){
            rs[tid]  = g_rad[bi*NN + tid];
            ds[tid]  = g_d0 [bi*NN + tid];
            ems[tid] = em[(size_t)bi*NN + tid];
        }
        float hiv = g_Hi[bi*HD + c];
        __syncthreads();   // rs/ds visible

        // ---- stage 1: m[j][c] = silu(Hi + Hj + rad*w0 + d0*w1) -> bf16 hi/lo ----
        {
            const float* Hjb = g_Hj + (size_t)b*NN*HD + c;
            int j0 = jg*48, j1 = j0+48;
            #pragma unroll 4
            for (int j=j0; j<j1; j++){
                float v = silu_f(hiv + Hjb[(size_t)j*HD] + rs[j]*w0 + ds[j]*w1);
                __nv_bfloat16 h16 = __float2bfloat16(v);
                __nv_bfloat16 l16 = __float2bfloat16(v - __bfloat162float(h16));
                mh[j*LDAB + c] = h16;
                ml[j*LDAB + c] = l16;
            }
        }
        __syncthreads();   // m ready

        // ---- MMA: warp (mw,nw) covers rows [mw*48,+48) x cols [nw*32,+32) ----
        {
            int rw = mw * 48;
            int cw = nw * 32;
            wmma::fragment<wmma::accumulator,16,16,16,float> acc[3][2];
            #pragma unroll
            for (int mi=0; mi<3; mi++)
                #pragma unroll
                for (int ni=0; ni<2; ni++) wmma::fill_fragment(acc[mi][ni], 0.0f);
            #pragma unroll
            for (int s=0; s<8; s++){
                wmma::fragment<wmma::matrix_a,16,16,16,__nv_bfloat16,wmma::row_major> ah[3], al[3];
                wmma::fragment<wmma::matrix_b,16,16,16,__nv_bfloat16,wmma::row_major> bh[2], bl[2];
                #pragma unroll
                for (int mi=0; mi<3; mi++){
                    wmma::load_matrix_sync(ah[mi], mh + (rw + mi*16)*LDAB + s*16, LDAB);
                    wmma::load_matrix_sync(al[mi], ml + (rw + mi*16)*LDAB + s*16, LDAB);
                }
                #pragma unroll
                for (int ni=0; ni<2; ni++){
                    wmma::load_matrix_sync(bh[ni], w2h + s*16*LDAB + cw + ni*16, LDAB);
                    wmma::load_matrix_sync(bl[ni], w2l + s*16*LDAB + cw + ni*16, LDAB);
                }
                #pragma unroll
                for (int mi=0; mi<3; mi++)
                    #pragma unroll
                    for (int ni=0; ni<2; ni++){
                        wmma::mma_sync(acc[mi][ni], ah[mi], bh[ni], acc[mi][ni]);
                        wmma::mma_sync(acc[mi][ni], ah[mi], bl[ni], acc[mi][ni]);
                        wmma::mma_sync(acc[mi][ni], al[mi], bh[ni], acc[mi][ni]);
                    }
            }
            #pragma unroll
            for (int mi=0; mi<3; mi++)
                #pragma unroll
                for (int ni=0; ni<2; ni++)
                    wmma::store_matrix_sync(outp + (rw + mi*16)*LDO + cw + ni*16,
                                            acc[mi][ni], LDO, wmma::mem_row_major);
        }
        __syncthreads();   // outp ready; m free for next tile

        // ---- epilogue ----
        if (COORD == 0){
            float s = 0.f;
            int j0 = jg*48, j1 = j0+48;
            #pragma unroll 4
            for (int j=j0; j<j1; j++)
                s += silu_f(outp[j*LDO + c] + b2c) * ems[j];
            part[jg*128 + c] = s;
            __syncthreads();
            if (tid < 128)
                g_agg[bi*HD + tid] = (part[tid] + part[128 + tid]) * 0.01f;
        } else {
            // threads 0..191: j = tid>>1, k-half = tid&1
            float v0=0.f, v1=0.f, v2=0.f;
            if (tid < 192){
                int j  = tid >> 1;
                int k0 = (tid & 1) * 64;
                const float* row = outp + j*LDO + k0;
                float s = 0.f;
                #pragma unroll 4
                for (int k=0; k<64; k++)
                    s += silu_f(row[k] + b2s[k0+k]) * w3s[k0+k];
                s += __shfl_xor_sync(0xffffffffu, s, 1);
                if ((tid & 1) == 0){
                    float sc = s * ems[j];
                    int eo = (bi*NN + j)*3;
                    v0 = g_cd[eo+0]*sc; v1 = g_cd[eo+1]*sc; v2 = g_cd[eo+2]*sc;
                }
            }
            #pragma unroll
            for (int off=16; off>1; off>>=1){
                v0 += __shfl_down_sync(0xffffffffu, v0, off);
                v1 += __shfl_down_sync(0xffffffffu, v1, off);
                v2 += __shfl_down_sync(0xffffffffu, v2, off);
            }
            // lane 0 of warps 0..5 holds partial (16 j each)
            if (tid < 192 && (tid & 31) == 0){
                int w = tid >> 5;
                part[w*4+0] = v0; part[w*4+1] = v1; part[w*4+2] = v2;
            }
            __syncthreads();
            if (tid < 3){
                float tot = part[tid] + part[4+tid] + part[8+tid]
                          + part[12+tid] + part[16+tid] + part[20+tid];
                g_x[bi*3 + tid] = (g_x[bi*3 + tid] + tot*0.01f) * nm[bi];
            }
        }
    }
}

// ---------------- output head ----------------
__global__ void k_out(const float* __restrict__ nm, const float* __restrict__ W_out,
                      const float* __restrict__ b_out, float* __restrict__ out){
    int b = blockIdx.x;
    int n = threadIdx.x;
    int node = b*NN + n;
    float mask = nm[node];
    float vx = (g_x[node*3+0] - g_x0[node*3+0]) * mask;
    float vy = (g_x[node*3+1] - g_x0[node*3+1]) * mask;
    float vz = (g_x[node*3+2] - g_x0[node*3+2]) * mask;
    float r0 = mask, r1 = vx, r2 = vy, r3 = vz;
    #pragma unroll
    for (int off=16; off>0; off>>=1){
        r0 += __shfl_down_sync(0xffffffffu, r0, off);
        r1 += __shfl_down_sync(0xffffffffu, r1, off);
        r2 += __shfl_down_sync(0xffffffffu, r2, off);
        r3 += __shfl_down_sync(0xffffffffu, r3, off);
    }
    __shared__ float part[3][4];
    int w = n >> 5;
    if ((n & 31) == 0){ part[w][0]=r0; part[w][1]=r1; part[w][2]=r2; part[w][3]=r3; }
    __syncthreads();
    float n_per = part[0][0] + part[1][0] + part[2][0];
    float sx    = part[0][1] + part[1][1] + part[2][1];
    float sy    = part[0][2] + part[1][2] + part[2][2];
    float sz    = part[0][3] + part[1][3] + part[2][3];
    float inv = 1.0f / n_per;
    out[node*9+0] = vx - sx*inv*mask;
    out[node*9+1] = vy - sy*inv*mask;
    out[node*9+2] = vz - sz*inv*mask;
    float acc[6];
    #pragma unroll
    for (int f=0; f<6; f++) acc[f] = b_out[f];
    const float* hrow = g_h + (size_t)node*HD;
    for (int k=0; k<HD; k++){
        float hv = hrow[k];
        #pragma unroll
        for (int f=0; f<6; f++) acc[f] += hv * W_out[k*7 + f];
    }
    #pragma unroll
    for (int f=0; f<6; f++) out[node*9+3+f] = acc[f] * mask;
}

// ---------------- launch ----------------
extern "C" void kernel_launch(void* const* d_in, const int* in_sizes, int n_in,
                              void* d_out, int out_size){
    (void)in_sizes; (void)n_in; (void)out_size;
    const float* xh    = (const float*)d_in[0];
    const float* t     = (const float*)d_in[1];
    const float* nm    = (const float*)d_in[2];
    const float* em    = (const float*)d_in[3];
    const float* W_emb = (const float*)d_in[4];
    const float* b_emb = (const float*)d_in[5];
    const float* gWe1  = (const float*)d_in[6];
    const float* gbe1  = (const float*)d_in[7];
    const float* gWe2  = (const float*)d_in[8];
    const float* gbe2  = (const float*)d_in[9];
    const float* gWn1  = (const float*)d_in[10];
    const float* gbn1  = (const float*)d_in[11];
    const float* gWn2  = (const float*)d_in[12];
    const float* gbn2  = (const float*)d_in[13];
    const float* eWc1  = (const float*)d_in[14];
    const float* ebc1  = (const float*)d_in[15];
    const float* eWc2  = (const float*)d_in[16];
    const float* ebc2  = (const float*)d_in[17];
    const float* eWc3  = (const float*)d_in[18];
    const float* W_out = (const float*)d_in[19];
    const float* b_out = (const float*)d_in[20];
    float* out = (float*)d_out;

    cudaFuncSetAttribute(k_edgeW<0>, cudaFuncAttributeMaxDynamicSharedMemorySize, SMEMB);
    cudaFuncSetAttribute(k_edgeW<1>, cudaFuncAttributeMaxDynamicSharedMemorySize, SMEMB);

    k_init<<<BN, HD>>>(xh, t, nm, W_emb, b_emb);
    k_radial<<<BN, NN>>>(0);

    for (int l=0; l<4; l++){
        k_radial<<<BN, NN>>>(1);
        for (int s=0; s<2; s++){
            int g = l*2 + s;
            k_hihj<<<BN/NPB, 256>>>(gWe1 + (size_t)g*258*HD, gbe1 + g*HD);
            k_edgeW<0><<<148, 256, SMEMB>>>(gWe1 + (size_t)g*258*HD, gWe2 + (size_t)g*HD*HD,
                                            gbe2 + g*HD, (const float*)0, em, nm);
            k_node<<<BN/NPB, 256>>>(gWn1 + (size_t)g*256*HD, gbn1 + g*HD,
                                    gWn2 + (size_t)g*HD*HD,  gbn2 + g*HD, nm);
        }
        k_hihj<<<BN/NPB, 256>>>(eWc1 + (size_t)l*258*HD, ebc1 + l*HD);
        k_edgeW<1><<<148, 256, SMEMB>>>(eWc1 + (size_t)l*258*HD, eWc2 + (size_t)l*HD*HD,
                                        ebc2 + l*HD, eWc3 + (size_t)l*HD, em, nm);
    }
    k_out<<<BSZ, NN>>>(nm, W_out, b_out, out);
}

// round 6
// speedup vs baseline: 1.4357x; 1.1084x over previous
#include <cuda_runtime.h>
#include <cuda_bf16.h>
#include <mma.h>
#include <cstdint>

using namespace nvcuda;

#define BSZ 16
#define NN  96
#define HD  128
#define BN  (BSZ*NN)
#define NPB 8

#define LDAB 136          // bf16 leading dim for m / W2 tiles
#define LDO  132          // fp32 leading dim for out tile

// ---- dynamic smem layout (bytes) ----
#define W2HI  0           // 128*136*2 = 34816
#define W2LO  34816
#define MHI   69632       // 96*136*2 = 26112
#define MLO   95744
#define OUTO  121856      // fp32 out[96][132] = 50688
#define RSO   172544
#define DSO   172928
#define EMO   173312
#define B2O   173696
#define W3O   174208
#define PARTO 174720      // 4*128 f = 2048
#define SMEMB 176768

// ---------------- scratch ----------------
__device__ float g_h  [BN*HD];
__device__ float g_Hi [BN*HD];
__device__ float g_Hj [BN*HD];
__device__ float g_agg[BN*HD];
__device__ float g_x  [BN*3];
__device__ float g_x0 [BN*3];
__device__ float g_rad[BN*NN];
__device__ float g_d0 [BN*NN];
__device__ float g_cd [BN*NN*3];

__device__ __forceinline__ float silu_f(float x){
    float e = __expf(-x);
    return __fdividef(x, 1.0f + e);
}

// ---------------- init ----------------
__global__ void k_init(const float* __restrict__ xh, const float* __restrict__ t,
                       const float* __restrict__ nm, const float* __restrict__ W_emb,
                       const float* __restrict__ b_emb){
    int n = blockIdx.x; int c = threadIdx.x;
    __shared__ float fs[8];
    float mask = nm[n];
    if (c < 6) fs[c] = xh[n*9 + 3 + c] * mask;
    if (c == 6) fs[6] = t[0];
    if (c < 3){ float v = xh[n*9 + c] * mask; g_x0[n*3+c] = v; g_x[n*3+c] = v; }
    __syncthreads();
    float a = b_emb[c];
    #pragma unroll
    for (int f=0; f<7; f++) a += fs[f] * W_emb[f*HD + c];
    g_h[n*HD + c] = a;
}

// ---------------- radial ----------------
__global__ void k_radial(int mode){
    int bi = blockIdx.x; int j = threadIdx.x;
    int b = bi / NN;
    const float* X = mode ? g_x : g_x0;
    float xi0 = X[bi*3+0], xi1 = X[bi*3+1], xi2 = X[bi*3+2];
    int nj = b*NN + j;
    float dx = xi0 - X[nj*3+0];
    float dy = xi1 - X[nj*3+1];
    float dz = xi2 - X[nj*3+2];
    float r = dx*dx + dy*dy + dz*dz;
    if (mode){
        g_rad[bi*NN + j] = r;
        float inv = rsqrtf(r + 1e-8f);
        int e = (bi*NN + j)*3;
        g_cd[e+0] = dx*inv; g_cd[e+1] = dy*inv; g_cd[e+2] = dz*inv;
    } else {
        g_d0[bi*NN + j] = r;
    }
}

// ---------------- Hi/Hj: 8 nodes/block, 256 threads, 4 nodes/thread ----------------
__global__ void __launch_bounds__(256) k_hihj(const float* __restrict__ W1, const float* __restrict__ b1){
    int n0 = blockIdx.x * NPB;
    int tid = threadIdx.x;
    int c = tid & 127;
    int u0 = (tid >> 7) * 4;        // nodes u0..u0+3
    __shared__ float hs[NPB][HD];
    for (int i = tid; i < NPB*HD; i += 256)
        hs[i>>7][i&127] = g_h[(n0 + (i>>7))*HD + (i&127)];
    __syncthreads();
    float bb = b1[c];
    float ai[4] = {bb,bb,bb,bb};
    float aj[4] = {0.f,0.f,0.f,0.f};
    #pragma unroll 4
    for (int k=0; k<HD; k++){
        float wi = W1[k*HD + c];
        float wj = W1[(HD+k)*HD + c];
        #pragma unroll
        for (int u=0; u<4; u++){
            float hv = hs[u0+u][k];
            ai[u] += hv*wi; aj[u] += hv*wj;
        }
    }
    #pragma unroll
    for (int u=0; u<4; u++){
        g_Hi[(n0+u0+u)*HD+c] = ai[u];
        g_Hj[(n0+u0+u)*HD+c] = aj[u];
    }
}

// ---------------- node update: 8 nodes/block, 256 threads, 4 nodes/thread ----------------
__global__ void __launch_bounds__(256) k_node(const float* __restrict__ Wn1, const float* __restrict__ bn1,
                       const float* __restrict__ Wn2, const float* __restrict__ bn2,
                       const float* __restrict__ nm){
    int n0 = blockIdx.x * NPB;
    int tid = threadIdx.x;
    int c = tid & 127;
    int u0 = (tid >> 7) * 4;
    __shared__ float hs[NPB][HD], as[NPB][HD], us[NPB][HD];
    for (int i = tid; i < NPB*HD; i += 256){
        int u = i>>7, cc = i&127;
        hs[u][cc] = g_h  [(n0+u)*HD+cc];
        as[u][cc] = g_agg[(n0+u)*HD+cc];
    }
    __syncthreads();
    float b1v = bn1[c];
    float a[4] = {b1v,b1v,b1v,b1v};
    #pragma unroll 4
    for (int k=0; k<HD; k++){
        float w1 = Wn1[k*HD + c], w2 = Wn1[(HD+k)*HD + c];
        #pragma unroll
        for (int u=0; u<4; u++)
            a[u] += hs[u0+u][k]*w1 + as[u0+u][k]*w2;
    }
    #pragma unroll
    for (int u=0; u<4; u++) us[u0+u][c] = silu_f(a[u]);
    __syncthreads();
    float b2v = bn2[c];
    #pragma unroll
    for (int u=0; u<4; u++) a[u] = b2v;
    #pragma unroll 4
    for (int k=0; k<HD; k++){
        float w = Wn2[k*HD + c];
        #pragma unroll
        for (int u=0; u<4; u++) a[u] += us[u0+u][k]*w;
    }
    #pragma unroll
    for (int u=0; u<4; u++)
        g_h[(n0+u0+u)*HD+c] = (hs[u0+u][c] + a[u]) * nm[n0+u0+u];
}

// ---------------- WMMA edge MLP (persistent, 512 thr, 2x8 warp tiling) ----------------
template<int COORD>
__global__ void __launch_bounds__(512,1) k_edgeW(const float* __restrict__ W1,
        const float* __restrict__ W2, const float* __restrict__ b2,
        const float* __restrict__ w3, const float* __restrict__ em,
        const float* __restrict__ nm){
    extern __shared__ char sm[];
    __nv_bfloat16* w2h = (__nv_bfloat16*)(sm + W2HI);
    __nv_bfloat16* w2l = (__nv_bfloat16*)(sm + W2LO);
    __nv_bfloat16* mh  = (__nv_bfloat16*)(sm + MHI);
    __nv_bfloat16* ml  = (__nv_bfloat16*)(sm + MLO);
    float* outp = (float*)(sm + OUTO);
    float* rs   = (float*)(sm + RSO);
    float* ds   = (float*)(sm + DSO);
    float* ems  = (float*)(sm + EMO);
    float* b2s  = (float*)(sm + B2O);
    float* w3s  = (float*)(sm + W3O);
    float* part = (float*)(sm + PARTO);

    int tid = threadIdx.x;
    int wid = tid >> 5;
    int mw  = wid >> 3;           // 0/1: M(j) group of 48
    int nw  = wid & 7;            // 0..7: N(c) group of 16
    int c   = tid & 127;
    int jg  = tid >> 7;           // 0..3: j-group of 24

    // ---- per-pass setup ----
    for (int idx = tid; idx < HD*HD; idx += 512){
        int k = idx >> 7, cc = idx & 127;
        float v = W2[idx];
        __nv_bfloat16 h16 = __float2bfloat16(v);
        __nv_bfloat16 l16 = __float2bfloat16(v - __bfloat162float(h16));
        w2h[k*LDAB + cc] = h16;
        w2l[k*LDAB + cc] = l16;
    }
    if (tid < 128){
        b2s[tid] = b2[tid];
        w3s[tid] = COORD ? w3[tid] : 0.f;
    }
    float w0 = W1[(2*HD)  *HD + c];
    float w1 = W1[(2*HD+1)*HD + c];
    float b2c = b2[c];

    for (int bi = blockIdx.x; bi < BN; bi += gridDim.x){
        int b = bi / NN;
        __syncthreads();   // prior epilogue reads complete

        if (tid < NN){
            rs[tid]  = g_rad[bi*NN + tid];
            ds[tid]  = g_d0 [bi*NN + tid];
            ems[tid] = em[(size_t)bi*NN + tid];
        }
        float hiv = g_Hi[bi*HD + c];
        __syncthreads();   // rs/ds visible

        // ---- stage 1: m[j][c] = silu(Hi + Hj + rad*w0 + d0*w1) -> bf16 hi/lo ----
        {
            const float* Hjb = g_Hj + (size_t)b*NN*HD + c;
            int j0 = jg*24, j1 = j0+24;
            #pragma unroll 4
            for (int j=j0; j<j1; j++){
                float v = silu_f(hiv + Hjb[(size_t)j*HD] + rs[j]*w0 + ds[j]*w1);
                __nv_bfloat16 h16 = __float2bfloat16(v);
                __nv_bfloat16 l16 = __float2bfloat16(v - __bfloat162float(h16));
                mh[j*LDAB + c] = h16;
                ml[j*LDAB + c] = l16;
            }
        }
        __syncthreads();   // m ready

        // ---- MMA: warp (mw,nw) covers rows [mw*48,+48) x cols [nw*16,+16) ----
        {
            int rw = mw * 48;
            int cw = nw * 16;
            wmma::fragment<wmma::accumulator,16,16,16,float> acc[3];
            #pragma unroll
            for (int mi=0; mi<3; mi++) wmma::fill_fragment(acc[mi], 0.0f);
            #pragma unroll
            for (int s=0; s<8; s++){
                wmma::fragment<wmma::matrix_a,16,16,16,__nv_bfloat16,wmma::row_major> ah[3], al[3];
                wmma::fragment<wmma::matrix_b,16,16,16,__nv_bfloat16,wmma::row_major> bh, bl;
                #pragma unroll
                for (int mi=0; mi<3; mi++){
                    wmma::load_matrix_sync(ah[mi], mh + (rw + mi*16)*LDAB + s*16, LDAB);
                    wmma::load_matrix_sync(al[mi], ml + (rw + mi*16)*LDAB + s*16, LDAB);
                }
                wmma::load_matrix_sync(bh, w2h + s*16*LDAB + cw, LDAB);
                wmma::load_matrix_sync(bl, w2l + s*16*LDAB + cw, LDAB);
                #pragma unroll
                for (int mi=0; mi<3; mi++){
                    wmma::mma_sync(acc[mi], ah[mi], bh, acc[mi]);
                    wmma::mma_sync(acc[mi], ah[mi], bl, acc[mi]);
                    wmma::mma_sync(acc[mi], al[mi], bh, acc[mi]);
                }
            }
            #pragma unroll
            for (int mi=0; mi<3; mi++)
                wmma::store_matrix_sync(outp + (rw + mi*16)*LDO + cw,
                                        acc[mi], LDO, wmma::mem_row_major);
        }
        __syncthreads();   // outp ready

        // ---- epilogue ----
        if (COORD == 0){
            float s = 0.f;
            int j0 = jg*24, j1 = j0+24;
            #pragma unroll 4
            for (int j=j0; j<j1; j++)
                s += silu_f(outp[j*LDO + c] + b2c) * ems[j];
            part[jg*128 + c] = s;
            __syncthreads();
            if (tid < 128)
                g_agg[bi*HD + tid] = (part[tid] + part[128+tid] + part[256+tid] + part[384+tid]) * 0.01f;
        } else {
            // threads 0..383: j = tid>>2, k-quarter = tid&3 (32 k each)
            float v0=0.f, v1=0.f, v2=0.f;
            if (tid < 384){
                int j  = tid >> 2;
                int k0 = (tid & 3) * 32;
                const float* row = outp + j*LDO + k0;
                float s = 0.f;
                #pragma unroll 4
                for (int k=0; k<32; k++)
                    s += silu_f(row[k] + b2s[k0+k]) * w3s[k0+k];
                s += __shfl_xor_sync(0xffffffffu, s, 1);
                s += __shfl_xor_sync(0xffffffffu, s, 2);
                if ((tid & 3) == 0){
                    float sc = s * ems[j];
                    int eo = (bi*NN + j)*3;
                    v0 = g_cd[eo+0]*sc; v1 = g_cd[eo+1]*sc; v2 = g_cd[eo+2]*sc;
                }
            }
            #pragma unroll
            for (int off=16; off>2; off>>=1){
                v0 += __shfl_down_sync(0xffffffffu, v0, off);
                v1 += __shfl_down_sync(0xffffffffu, v1, off);
                v2 += __shfl_down_sync(0xffffffffu, v2, off);
            }
            if (tid < 384 && (tid & 31) == 0){
                int w = tid >> 5;      // 0..11
                part[w*4+0] = v0; part[w*4+1] = v1; part[w*4+2] = v2;
            }
            __syncthreads();
            if (tid < 3){
                float tot = 0.f;
                #pragma unroll
                for (int w=0; w<12; w++) tot += part[w*4+tid];
                g_x[bi*3 + tid] = (g_x[bi*3 + tid] + tot*0.01f) * nm[bi];
            }
        }
    }
}

// ---------------- output head ----------------
__global__ void k_out(const float* __restrict__ nm, const float* __restrict__ W_out,
                      const float* __restrict__ b_out, float* __restrict__ out){
    int b = blockIdx.x;
    int n = threadIdx.x;
    int node = b*NN + n;
    float mask = nm[node];
    float vx = (g_x[node*3+0] - g_x0[node*3+0]) * mask;
    float vy = (g_x[node*3+1] - g_x0[node*3+1]) * mask;
    float vz = (g_x[node*3+2] - g_x0[node*3+2]) * mask;
    float r0 = mask, r1 = vx, r2 = vy, r3 = vz;
    #pragma unroll
    for (int off=16; off>0; off>>=1){
        r0 += __shfl_down_sync(0xffffffffu, r0, off);
        r1 += __shfl_down_sync(0xffffffffu, r1, off);
        r2 += __shfl_down_sync(0xffffffffu, r2, off);
        r3 += __shfl_down_sync(0xffffffffu, r3, off);
    }
    __shared__ float part[3][4];
    int w = n >> 5;
    if ((n & 31) == 0){ part[w][0]=r0; part[w][1]=r1; part[w][2]=r2; part[w][3]=r3; }
    __syncthreads();
    float n_per = part[0][0] + part[1][0] + part[2][0];
    float sx    = part[0][1] + part[1][1] + part[2][1];
    float sy    = part[0][2] + part[1][2] + part[2][2];
    float sz    = part[0][3] + part[1][3] + part[2][3];
    float inv = 1.0f / n_per;
    out[node*9+0] = vx - sx*inv*mask;
    out[node*9+1] = vy - sy*inv*mask;
    out[node*9+2] = vz - sz*inv*mask;
    float acc[6];
    #pragma unroll
    for (int f=0; f<6; f++) acc[f] = b_out[f];
    const float* hrow = g_h + (size_t)node*HD;
    for (int k=0; k<HD; k++){
        float hv = hrow[k];
        #pragma unroll
        for (int f=0; f<6; f++) acc[f] += hv * W_out[k*7 + f];
    }
    #pragma unroll
    for (int f=0; f<6; f++) out[node*9+3+f] = acc[f] * mask;
}

// ---------------- launch ----------------
extern "C" void kernel_launch(void* const* d_in, const int* in_sizes, int n_in,
                              void* d_out, int out_size){
    (void)in_sizes; (void)n_in; (void)out_size;
    const float* xh    = (const float*)d_in[0];
    const float* t     = (const float*)d_in[1];
    const float* nm    = (const float*)d_in[2];
    const float* em    = (const float*)d_in[3];
    const float* W_emb = (const float*)d_in[4];
    const float* b_emb = (const float*)d_in[5];
    const float* gWe1  = (const float*)d_in[6];
    const float* gbe1  = (const float*)d_in[7];
    const float* gWe2  = (const float*)d_in[8];
    const float* gbe2  = (const float*)d_in[9];
    const float* gWn1  = (const float*)d_in[10];
    const float* gbn1  = (const float*)d_in[11];
    const float* gWn2  = (const float*)d_in[12];
    const float* gbn2  = (const float*)d_in[13];
    const float* eWc1  = (const float*)d_in[14];
    const float* ebc1  = (const float*)d_in[15];
    const float* eWc2  = (const float*)d_in[16];
    const float* ebc2  = (const float*)d_in[17];
    const float* eWc3  = (const float*)d_in[18];
    const float* W_out = (const float*)d_in[19];
    const float* b_out = (const float*)d_in[20];
    float* out = (float*)d_out;

    cudaFuncSetAttribute(k_edgeW<0>, cudaFuncAttributeMaxDynamicSharedMemorySize, SMEMB);
    cudaFuncSetAttribute(k_edgeW<1>, cudaFuncAttributeMaxDynamicSharedMemorySize, SMEMB);

    k_init<<<BN, HD>>>(xh, t, nm, W_emb, b_emb);
    k_radial<<<BN, NN>>>(0);

    for (int l=0; l<4; l++){
        k_radial<<<BN, NN>>>(1);
        for (int s=0; s<2; s++){
            int g = l*2 + s;
            k_hihj<<<BN/NPB, 256>>>(gWe1 + (size_t)g*258*HD, gbe1 + g*HD);
            k_edgeW<0><<<148, 512, SMEMB>>>(gWe1 + (size_t)g*258*HD, gWe2 + (size_t)g*HD*HD,
                                            gbe2 + g*HD, (const float*)0, em, nm);
            k_node<<<BN/NPB, 256>>>(gWn1 + (size_t)g*256*HD, gbn1 + g*HD,
                                    gWn2 + (size_t)g*HD*HD,  gbn2 + g*HD, nm);
        }
        k_hihj<<<BN/NPB, 256>>>(eWc1 + (size_t)l*258*HD, ebc1 + l*HD);
        k_edgeW<1><<<148, 512, SMEMB>>>(eWc1 + (size_t)l*258*HD, eWc2 + (size_t)l*HD*HD,
                                        ebc2 + l*HD, eWc3 + (size_t)l*HD, em, nm);
    }
    k_out<<<BSZ, NN>>>(nm, W_out, b_out, out);
}